// round 5
// baseline (speedup 1.0000x reference)
#include <cuda_runtime.h>
#include <math.h>

// Problem constants (inp shape (4096, 9, 2048) fp32, out (3, 2048) fp32)
#define T_STEPS 4096
#define NB      2048
#define CHUNK   4
#define NG      (T_STEPS / CHUNK)   // 1024 chunk-steps
#define NSEG    16
#define SEGLEN  (NG / NSEG)         // 64 chunks per segment
#define WARM    16                  // warmup chunks (64 raw steps)
#define DEPTH   4                   // smem pipeline depth (power of 2)
#define NBGRP   (NB / 128)          // 16 batch groups

// Per-segment partial log-sums: [3 cols][NSEG][NB]
__device__ float g_part[3 * NSEG * NB];
// Completion counters, one per batch group (zero-init; reset by finisher)
__device__ int g_cnt[NBGRP];

__device__ __forceinline__ float rcp_approx(float x) {
    float r;
    asm("rcp.approx.f32 %0, %1;" : "=f"(r) : "f"(x));
    return r;
}

__device__ __forceinline__ void rescale3(float nsq, float& x, float& y, float& z, int& S) {
    int e = (__float_as_int(nsq) >> 23) - 127;
    int s = e >> 1;                                  // floor(e/2)
    float sc = __int_as_float((127 - s) << 23);      // 2^{-s}
    x *= sc; y *= sc; z *= sc;
    S += s;
}

__device__ __forceinline__ void cp16(float* smem_dst, const float* gmem_src) {
    unsigned d = (unsigned)__cvta_generic_to_shared(smem_dst);
    asm volatile("cp.async.cg.shared.global [%0], [%1], 16;\n" :: "r"(d), "l"(gmem_src));
}

// ---------------------------------------------------------------------------
// Fused kernel with cp.async smem pipeline + in-kernel deterministic
// reduction epilogue (last segment-block per batch group sums all partials
// in fixed segment order and writes the final output; no second launch).
// ---------------------------------------------------------------------------
__global__ __launch_bounds__(128) void fused_scan_kernel(const float* __restrict__ inp,
                                                          float* __restrict__ out) {
    extern __shared__ float sbuf[];                  // [DEPTH][36][128]
    __shared__ int sh_old;
    const int tid = threadIdx.x;
    const int bx  = blockIdx.x;
    const int b0  = bx * 128;
    const int b   = b0 + tid;
    const int s   = blockIdx.y;
    const int segStart = s * SEGLEN;
    int g0 = segStart - WARM; if (g0 < 0) g0 = 0;
    const int gEnd = segStart + SEGLEN;

    // Q columns (identity start; warmed up for s>0)
    float q0x = 1.f, q0y = 0.f, q0z = 0.f;
    float q1x = 0.f, q1y = 1.f, q1z = 0.f;
    float q2x = 0.f, q2y = 0.f, q2z = 1.f;
    int S0 = 0, S1 = 0, S2 = 0;

    // Producer: stage chunk c into smem ring slot c & (DEPTH-1).
    // 36 rows of 512B each; 1152 16B ops per block = 9 per thread.
    auto issue_chunk = [&](int c) {
        int buf = c & (DEPTH - 1);
#pragma unroll
        for (int k = 0; k < 9; k++) {
            int idx = tid + k * 128;                 // 0..1151
            int j = idx >> 5;                        // plane 0..35
            int l = idx & 31;                        // 16B lane within row
            const float* src = inp + (size_t)(c * 36 + j) * NB + b0 + l * 4;
            float* dst = sbuf + ((buf * 36 + j) * 128 + l * 4);
            cp16(dst, src);
        }
        asm volatile("cp.async.commit_group;\n" ::: "memory");
    };

    // Prologue: fill the pipeline
#pragma unroll
    for (int c = 0; c < DEPTH; c++) issue_chunk(g0 + c);

    for (int g = g0; g < gEnd; g++) {
        asm volatile("cp.async.wait_group %0;\n" :: "n"(DEPTH - 1) : "memory");
        __syncthreads();                             // writes visible block-wide

        const float* J = sbuf + (size_t)(g & (DEPTH - 1)) * 36 * 128 + tid;

        // Apply 4 Jacobians to all three Q columns: Q <- J_t * Q
        float m0x = q0x, m0y = q0y, m0z = q0z;
        float m1x = q1x, m1y = q1y, m1z = q1z;
        float m2x = q2x, m2y = q2y, m2z = q2z;
#pragma unroll
        for (int t = 0; t < CHUNK; t++) {
            float j0 = J[(t*9+0)*128], j1 = J[(t*9+1)*128], j2 = J[(t*9+2)*128];
            float j3 = J[(t*9+3)*128], j4 = J[(t*9+4)*128], j5 = J[(t*9+5)*128];
            float j6 = J[(t*9+6)*128], j7 = J[(t*9+7)*128], j8 = J[(t*9+8)*128];
            float a0 = fmaf(j0, m0x, fmaf(j1, m0y, j2 * m0z));
            float a1 = fmaf(j3, m0x, fmaf(j4, m0y, j5 * m0z));
            float a2 = fmaf(j6, m0x, fmaf(j7, m0y, j8 * m0z));
            float c0 = fmaf(j0, m1x, fmaf(j1, m1y, j2 * m1z));
            float c1 = fmaf(j3, m1x, fmaf(j4, m1y, j5 * m1z));
            float c2 = fmaf(j6, m1x, fmaf(j7, m1y, j8 * m1z));
            float e0 = fmaf(j0, m2x, fmaf(j1, m2y, j2 * m2z));
            float e1 = fmaf(j3, m2x, fmaf(j4, m2y, j5 * m2z));
            float e2 = fmaf(j6, m2x, fmaf(j7, m2y, j8 * m2z));
            m0x = a0; m0y = a1; m0z = a2;
            m1x = c0; m1y = c1; m1z = c2;
            m2x = e0; m2y = e1; m2z = e2;
        }

        __syncthreads();                             // all threads done with slot
        if (g + DEPTH < gEnd) issue_chunk(g + DEPTH);
        else asm volatile("cp.async.commit_group;\n" ::: "memory");

        // Classical Gram-Schmidt (matches reference), unnormalized betas
        float n0 = fmaf(m0x, m0x, fmaf(m0y, m0y, m0z * m0z));
        float r0 = rcp_approx(n0);

        float d01 = fmaf(m0x, m1x, fmaf(m0y, m1y, m0z * m1z));
        float c01 = d01 * r0;
        float b1x = fmaf(-c01, m0x, m1x);
        float b1y = fmaf(-c01, m0y, m1y);
        float b1z = fmaf(-c01, m0z, m1z);
        float n1 = fmaf(b1x, b1x, fmaf(b1y, b1y, b1z * b1z));
        float r1 = rcp_approx(n1);

        float d02 = fmaf(m0x, m2x, fmaf(m0y, m2y, m0z * m2z));
        float c02 = d02 * r0;
        float d12 = fmaf(b1x, m2x, fmaf(b1y, m2y, b1z * m2z));
        float c12 = d12 * r1;
        float b2x = fmaf(-c12, b1x, fmaf(-c02, m0x, m2x));
        float b2y = fmaf(-c12, b1y, fmaf(-c02, m0y, m2y));
        float b2z = fmaf(-c12, b1z, fmaf(-c02, m0z, m2z));
        float n2 = fmaf(b2x, b2x, fmaf(b2y, b2y, b2z * b2z));

        q0x = m0x; q0y = m0y; q0z = m0z;
        rescale3(n0, q0x, q0y, q0z, S0);
        q1x = b1x; q1y = b1y; q1z = b1z;
        rescale3(n1, q1x, q1y, q1z, S1);
        q2x = b2x; q2y = b2y; q2z = b2z;
        rescale3(n2, q2x, q2y, q2z, S2);

        // Segment boundary: exact-normalize Q, reset exponent counters
        if (g == segStart - 1) {
            float f0 = fmaf(q0x, q0x, fmaf(q0y, q0y, q0z * q0z));
            float f1 = fmaf(q1x, q1x, fmaf(q1y, q1y, q1z * q1z));
            float f2 = fmaf(q2x, q2x, fmaf(q2y, q2y, q2z * q2z));
            float i0 = 1.0f / sqrtf(f0);
            float i1 = 1.0f / sqrtf(f1);
            float i2 = 1.0f / sqrtf(f2);
            q0x *= i0; q0y *= i0; q0z *= i0;
            q1x *= i1; q1y *= i1; q1z *= i1;
            q2x *= i2; q2y *= i2; q2z *= i2;
            S0 = S1 = S2 = 0;
        }
    }

    const float LN2 = 0.69314718055994531f;
    float f0 = fmaf(q0x, q0x, fmaf(q0y, q0y, q0z * q0z));
    float f1 = fmaf(q1x, q1x, fmaf(q1y, q1y, q1z * q1z));
    float f2 = fmaf(q2x, q2x, fmaf(q2y, q2y, q2z * q2z));

    g_part[(0 * NSEG + s) * NB + b] = 0.5f * logf(f0) + (float)S0 * LN2;
    g_part[(1 * NSEG + s) * NB + b] = 0.5f * logf(f1) + (float)S1 * LN2;
    g_part[(2 * NSEG + s) * NB + b] = 0.5f * logf(f2) + (float)S2 * LN2;

    // -------- In-kernel reduction epilogue (last block per batch group) ----
    __threadfence();                                 // publish partials
    if (tid == 0) sh_old = atomicAdd(&g_cnt[bx], 1);
    __syncthreads();

    if (sh_old == NSEG - 1) {
        __threadfence();                             // acquire all partials
        const float INV_TDT = 1.0f / ((float)T_STEPS * 0.01f);   // 1/40.96
#pragma unroll
        for (int c = 0; c < 3; c++) {
            float sum = 0.f;
#pragma unroll
            for (int ss = 0; ss < NSEG; ss++)        // fixed order: deterministic
                sum += g_part[(c * NSEG + ss) * NB + b];
            out[c * NB + b] = sum * INV_TDT;
        }
        if (tid == 0) g_cnt[bx] = 0;                 // restore state for replay
    }
}

extern "C" void kernel_launch(void* const* d_in, const int* in_sizes, int n_in,
                              void* d_out, int out_size) {
    const float* inp = (const float*)d_in[0];
    float* out = (float*)d_out;
    (void)in_sizes; (void)n_in; (void)out_size;

    const int smem_bytes = DEPTH * 36 * 128 * sizeof(float);  // 73728 B
    static bool attr_done = false;  // idempotent host-side attribute, not a graph op
    if (!attr_done) {
        cudaFuncSetAttribute(fused_scan_kernel,
                             cudaFuncAttributeMaxDynamicSharedMemorySize, smem_bytes);
        attr_done = true;
    }

    dim3 g(NBGRP, NSEG);
    fused_scan_kernel<<<g, 128, smem_bytes>>>(inp, out);
}

// round 6
// speedup vs baseline: 1.2734x; 1.2734x over previous
#include <cuda_runtime.h>
#include <math.h>

// Problem constants (inp shape (4096, 9, 2048) fp32, out (3, 2048) fp32)
#define T_STEPS 4096
#define NB      2048
#define CHUNK   4
#define NG      (T_STEPS / CHUNK)   // 1024 chunk-steps
#define NSEG    16
#define SEGLEN  (NG / NSEG)         // 64 chunks per segment
#define WARM    8                   // warmup chunks (32 raw steps)
#define DEPTH   4                   // smem pipeline depth (power of 2)

// Per-segment partial log-sums: [3 cols][NSEG][NB]
__device__ float g_part[3 * NSEG * NB];

__device__ __forceinline__ float rcp_approx(float x) {
    float r;
    asm("rcp.approx.f32 %0, %1;" : "=f"(r) : "f"(x));
    return r;
}

__device__ __forceinline__ void rescale3(float nsq, float& x, float& y, float& z, int& S) {
    int e = (__float_as_int(nsq) >> 23) - 127;
    int s = e >> 1;                                  // floor(e/2)
    float sc = __int_as_float((127 - s) << 23);      // 2^{-s}
    x *= sc; y *= sc; z *= sc;
    S += s;
}

__device__ __forceinline__ void cp16(float* smem_dst, const float* gmem_src) {
    unsigned d = (unsigned)__cvta_generic_to_shared(smem_dst);
    asm volatile("cp.async.cg.shared.global [%0], [%1], 16;\n" :: "r"(d), "l"(gmem_src));
}

// ---------------------------------------------------------------------------
// Fused kernel with cp.async smem pipeline. Block = 128 threads = 128 batch
// lanes; blockIdx.y = segment. Each chunk (4 Jacobians, 36 planes x 128
// floats = 18 KB) is staged through a DEPTH-deep smem ring, loaded as
// 16B cp.async ops (block-cooperative, fully coalesced).
// NO fences/atomics in this kernel — R5 showed they wreck loop scheduling.
// ---------------------------------------------------------------------------
__global__ __launch_bounds__(128) void fused_scan_kernel(const float* __restrict__ inp) {
    extern __shared__ float sbuf[];                  // [DEPTH][36][128]
    const int tid = threadIdx.x;
    const int b0  = blockIdx.x * 128;
    const int b   = b0 + tid;
    const int s   = blockIdx.y;
    const int segStart = s * SEGLEN;
    int g0 = segStart - WARM; if (g0 < 0) g0 = 0;
    const int gEnd = segStart + SEGLEN;

    // Q columns (identity start; warmed up for s>0)
    float q0x = 1.f, q0y = 0.f, q0z = 0.f;
    float q1x = 0.f, q1y = 1.f, q1z = 0.f;
    float q2x = 0.f, q2y = 0.f, q2z = 1.f;
    int S0 = 0, S1 = 0, S2 = 0;

    // Producer: stage chunk c into smem ring slot c & (DEPTH-1).
    // 36 rows of 512B each; 1152 16B ops per block = 9 per thread.
    auto issue_chunk = [&](int c) {
        int buf = c & (DEPTH - 1);
#pragma unroll
        for (int k = 0; k < 9; k++) {
            int idx = tid + k * 128;                 // 0..1151
            int j = idx >> 5;                        // plane 0..35
            int l = idx & 31;                        // 16B lane within row
            const float* src = inp + (size_t)(c * 36 + j) * NB + b0 + l * 4;
            float* dst = sbuf + ((buf * 36 + j) * 128 + l * 4);
            cp16(dst, src);
        }
        asm volatile("cp.async.commit_group;\n" ::: "memory");
    };

    // Prologue: fill the pipeline
#pragma unroll
    for (int c = 0; c < DEPTH; c++) issue_chunk(g0 + c);

    for (int g = g0; g < gEnd; g++) {
        asm volatile("cp.async.wait_group %0;\n" :: "n"(DEPTH - 1) : "memory");
        __syncthreads();                             // writes visible block-wide

        const float* J = sbuf + (size_t)(g & (DEPTH - 1)) * 36 * 128 + tid;

        // Apply 4 Jacobians to all three Q columns: Q <- J_t * Q
        float m0x = q0x, m0y = q0y, m0z = q0z;
        float m1x = q1x, m1y = q1y, m1z = q1z;
        float m2x = q2x, m2y = q2y, m2z = q2z;
#pragma unroll
        for (int t = 0; t < CHUNK; t++) {
            float j0 = J[(t*9+0)*128], j1 = J[(t*9+1)*128], j2 = J[(t*9+2)*128];
            float j3 = J[(t*9+3)*128], j4 = J[(t*9+4)*128], j5 = J[(t*9+5)*128];
            float j6 = J[(t*9+6)*128], j7 = J[(t*9+7)*128], j8 = J[(t*9+8)*128];
            float a0 = fmaf(j0, m0x, fmaf(j1, m0y, j2 * m0z));
            float a1 = fmaf(j3, m0x, fmaf(j4, m0y, j5 * m0z));
            float a2 = fmaf(j6, m0x, fmaf(j7, m0y, j8 * m0z));
            float c0 = fmaf(j0, m1x, fmaf(j1, m1y, j2 * m1z));
            float c1 = fmaf(j3, m1x, fmaf(j4, m1y, j5 * m1z));
            float c2 = fmaf(j6, m1x, fmaf(j7, m1y, j8 * m1z));
            float e0 = fmaf(j0, m2x, fmaf(j1, m2y, j2 * m2z));
            float e1 = fmaf(j3, m2x, fmaf(j4, m2y, j5 * m2z));
            float e2 = fmaf(j6, m2x, fmaf(j7, m2y, j8 * m2z));
            m0x = a0; m0y = a1; m0z = a2;
            m1x = c0; m1y = c1; m1z = c2;
            m2x = e0; m2y = e1; m2z = e2;
        }

        __syncthreads();                             // all threads done with slot
        if (g + DEPTH < gEnd) issue_chunk(g + DEPTH);
        else asm volatile("cp.async.commit_group;\n" ::: "memory");

        // Classical Gram-Schmidt (matches reference), unnormalized betas
        float n0 = fmaf(m0x, m0x, fmaf(m0y, m0y, m0z * m0z));
        float r0 = rcp_approx(n0);

        float d01 = fmaf(m0x, m1x, fmaf(m0y, m1y, m0z * m1z));
        float c01 = d01 * r0;
        float b1x = fmaf(-c01, m0x, m1x);
        float b1y = fmaf(-c01, m0y, m1y);
        float b1z = fmaf(-c01, m0z, m1z);
        float n1 = fmaf(b1x, b1x, fmaf(b1y, b1y, b1z * b1z));
        float r1 = rcp_approx(n1);

        float d02 = fmaf(m0x, m2x, fmaf(m0y, m2y, m0z * m2z));
        float c02 = d02 * r0;
        float d12 = fmaf(b1x, m2x, fmaf(b1y, m2y, b1z * m2z));
        float c12 = d12 * r1;
        float b2x = fmaf(-c12, b1x, fmaf(-c02, m0x, m2x));
        float b2y = fmaf(-c12, b1y, fmaf(-c02, m0y, m2y));
        float b2z = fmaf(-c12, b1z, fmaf(-c02, m0z, m2z));
        float n2 = fmaf(b2x, b2x, fmaf(b2y, b2y, b2z * b2z));

        q0x = m0x; q0y = m0y; q0z = m0z;
        rescale3(n0, q0x, q0y, q0z, S0);
        q1x = b1x; q1y = b1y; q1z = b1z;
        rescale3(n1, q1x, q1y, q1z, S1);
        q2x = b2x; q2y = b2y; q2z = b2z;
        rescale3(n2, q2x, q2y, q2z, S2);

        // Segment boundary: exact-normalize Q, reset exponent counters
        if (g == segStart - 1) {
            float f0 = fmaf(q0x, q0x, fmaf(q0y, q0y, q0z * q0z));
            float f1 = fmaf(q1x, q1x, fmaf(q1y, q1y, q1z * q1z));
            float f2 = fmaf(q2x, q2x, fmaf(q2y, q2y, q2z * q2z));
            float i0 = 1.0f / sqrtf(f0);
            float i1 = 1.0f / sqrtf(f1);
            float i2 = 1.0f / sqrtf(f2);
            q0x *= i0; q0y *= i0; q0z *= i0;
            q1x *= i1; q1y *= i1; q1z *= i1;
            q2x *= i2; q2y *= i2; q2z *= i2;
            S0 = S1 = S2 = 0;
        }
    }

    const float LN2 = 0.69314718055994531f;
    float f0 = fmaf(q0x, q0x, fmaf(q0y, q0y, q0z * q0z));
    float f1 = fmaf(q1x, q1x, fmaf(q1y, q1y, q1z * q1z));
    float f2 = fmaf(q2x, q2x, fmaf(q2y, q2y, q2z * q2z));

    g_part[(0 * NSEG + s) * NB + b] = 0.5f * logf(f0) + (float)S0 * LN2;
    g_part[(1 * NSEG + s) * NB + b] = 0.5f * logf(f1) + (float)S1 * LN2;
    g_part[(2 * NSEG + s) * NB + b] = 0.5f * logf(f2) + (float)S2 * LN2;
}

// ---------------------------------------------------------------------------
// Deterministic reduction over segments
// ---------------------------------------------------------------------------
__global__ __launch_bounds__(128) void reduce_kernel(float* __restrict__ out) {
    int i = blockIdx.x * 128 + threadIdx.x;          // 0 .. 3*NB-1
    int c = i / NB;
    int b = i - c * NB;
    float sum = 0.f;
#pragma unroll
    for (int s = 0; s < NSEG; s++)
        sum += g_part[(c * NSEG + s) * NB + b];
    const float INV_TDT = 1.0f / ((float)T_STEPS * 0.01f);   // 1/40.96
    out[i] = sum * INV_TDT;
}

extern "C" void kernel_launch(void* const* d_in, const int* in_sizes, int n_in,
                              void* d_out, int out_size) {
    const float* inp = (const float*)d_in[0];
    float* out = (float*)d_out;
    (void)in_sizes; (void)n_in; (void)out_size;

    const int smem_bytes = DEPTH * 36 * 128 * sizeof(float);  // 73728 B
    static bool attr_done = false;  // idempotent host-side attribute, not a graph op
    if (!attr_done) {
        cudaFuncSetAttribute(fused_scan_kernel,
                             cudaFuncAttributeMaxDynamicSharedMemorySize, smem_bytes);
        attr_done = true;
    }

    dim3 g(NB / 128, NSEG);
    fused_scan_kernel<<<g, 128, smem_bytes>>>(inp);
    reduce_kernel<<<(3 * NB) / 128, 128>>>(out);
}

// round 7
// speedup vs baseline: 1.2901x; 1.0131x over previous
#include <cuda_runtime.h>
#include <math.h>

// Problem constants (inp shape (4096, 9, 2048) fp32, out (3, 2048) fp32)
#define T_STEPS 4096
#define NB      2048
#define CHUNK   4
#define NG      (T_STEPS / CHUNK)   // 1024 chunk-steps
#define NSEG    16
#define SEGLEN  (NG / NSEG)         // 64 chunks per segment
#define WARM    8                   // warmup chunks (32 raw steps)
#define DEPTH   4                   // smem pipeline depth (power of 2)

// Per-segment partial log-sums: [3 cols][NSEG][NB]
__device__ float g_part[3 * NSEG * NB];

__device__ __forceinline__ float rcp_approx(float x) {
    float r;
    asm("rcp.approx.f32 %0, %1;" : "=f"(r) : "f"(x));
    return r;
}

__device__ __forceinline__ void rescale3(float nsq, float& x, float& y, float& z, int& S) {
    int e = (__float_as_int(nsq) >> 23) - 127;
    int s = e >> 1;                                  // floor(e/2)
    float sc = __int_as_float((127 - s) << 23);      // 2^{-s}
    x *= sc; y *= sc; z *= sc;
    S += s;
}

__device__ __forceinline__ void cp16(float* smem_dst, const float* gmem_src) {
    unsigned d = (unsigned)__cvta_generic_to_shared(smem_dst);
    asm volatile("cp.async.cg.shared.global [%0], [%1], 16;\n" :: "r"(d), "l"(gmem_src));
}

// ---------------------------------------------------------------------------
// Fused kernel with cp.async smem pipeline. BYTE-IDENTICAL loop to R6 —
// it sits at its DRAM traffic floor (302 MB unique @ ~6.3 TB/s ceiling).
// NO fences/atomics in this kernel (R5 lesson).
// ---------------------------------------------------------------------------
__global__ __launch_bounds__(128) void fused_scan_kernel(const float* __restrict__ inp) {
    extern __shared__ float sbuf[];                  // [DEPTH][36][128]
    const int tid = threadIdx.x;
    const int b0  = blockIdx.x * 128;
    const int b   = b0 + tid;
    const int s   = blockIdx.y;
    const int segStart = s * SEGLEN;
    int g0 = segStart - WARM; if (g0 < 0) g0 = 0;
    const int gEnd = segStart + SEGLEN;

    // Q columns (identity start; warmed up for s>0)
    float q0x = 1.f, q0y = 0.f, q0z = 0.f;
    float q1x = 0.f, q1y = 1.f, q1z = 0.f;
    float q2x = 0.f, q2y = 0.f, q2z = 1.f;
    int S0 = 0, S1 = 0, S2 = 0;

    // Producer: stage chunk c into smem ring slot c & (DEPTH-1).
    auto issue_chunk = [&](int c) {
        int buf = c & (DEPTH - 1);
#pragma unroll
        for (int k = 0; k < 9; k++) {
            int idx = tid + k * 128;                 // 0..1151
            int j = idx >> 5;                        // plane 0..35
            int l = idx & 31;                        // 16B lane within row
            const float* src = inp + (size_t)(c * 36 + j) * NB + b0 + l * 4;
            float* dst = sbuf + ((buf * 36 + j) * 128 + l * 4);
            cp16(dst, src);
        }
        asm volatile("cp.async.commit_group;\n" ::: "memory");
    };

    // Prologue: fill the pipeline
#pragma unroll
    for (int c = 0; c < DEPTH; c++) issue_chunk(g0 + c);

    for (int g = g0; g < gEnd; g++) {
        asm volatile("cp.async.wait_group %0;\n" :: "n"(DEPTH - 1) : "memory");
        __syncthreads();                             // writes visible block-wide

        const float* J = sbuf + (size_t)(g & (DEPTH - 1)) * 36 * 128 + tid;

        // Apply 4 Jacobians to all three Q columns: Q <- J_t * Q
        float m0x = q0x, m0y = q0y, m0z = q0z;
        float m1x = q1x, m1y = q1y, m1z = q1z;
        float m2x = q2x, m2y = q2y, m2z = q2z;
#pragma unroll
        for (int t = 0; t < CHUNK; t++) {
            float j0 = J[(t*9+0)*128], j1 = J[(t*9+1)*128], j2 = J[(t*9+2)*128];
            float j3 = J[(t*9+3)*128], j4 = J[(t*9+4)*128], j5 = J[(t*9+5)*128];
            float j6 = J[(t*9+6)*128], j7 = J[(t*9+7)*128], j8 = J[(t*9+8)*128];
            float a0 = fmaf(j0, m0x, fmaf(j1, m0y, j2 * m0z));
            float a1 = fmaf(j3, m0x, fmaf(j4, m0y, j5 * m0z));
            float a2 = fmaf(j6, m0x, fmaf(j7, m0y, j8 * m0z));
            float c0 = fmaf(j0, m1x, fmaf(j1, m1y, j2 * m1z));
            float c1 = fmaf(j3, m1x, fmaf(j4, m1y, j5 * m1z));
            float c2 = fmaf(j6, m1x, fmaf(j7, m1y, j8 * m1z));
            float e0 = fmaf(j0, m2x, fmaf(j1, m2y, j2 * m2z));
            float e1 = fmaf(j3, m2x, fmaf(j4, m2y, j5 * m2z));
            float e2 = fmaf(j6, m2x, fmaf(j7, m2y, j8 * m2z));
            m0x = a0; m0y = a1; m0z = a2;
            m1x = c0; m1y = c1; m1z = c2;
            m2x = e0; m2y = e1; m2z = e2;
        }

        __syncthreads();                             // all threads done with slot
        if (g + DEPTH < gEnd) issue_chunk(g + DEPTH);
        else asm volatile("cp.async.commit_group;\n" ::: "memory");

        // Classical Gram-Schmidt (matches reference), unnormalized betas
        float n0 = fmaf(m0x, m0x, fmaf(m0y, m0y, m0z * m0z));
        float r0 = rcp_approx(n0);

        float d01 = fmaf(m0x, m1x, fmaf(m0y, m1y, m0z * m1z));
        float c01 = d01 * r0;
        float b1x = fmaf(-c01, m0x, m1x);
        float b1y = fmaf(-c01, m0y, m1y);
        float b1z = fmaf(-c01, m0z, m1z);
        float n1 = fmaf(b1x, b1x, fmaf(b1y, b1y, b1z * b1z));
        float r1 = rcp_approx(n1);

        float d02 = fmaf(m0x, m2x, fmaf(m0y, m2y, m0z * m2z));
        float c02 = d02 * r0;
        float d12 = fmaf(b1x, m2x, fmaf(b1y, m2y, b1z * m2z));
        float c12 = d12 * r1;
        float b2x = fmaf(-c12, b1x, fmaf(-c02, m0x, m2x));
        float b2y = fmaf(-c12, b1y, fmaf(-c02, m0y, m2y));
        float b2z = fmaf(-c12, b1z, fmaf(-c02, m0z, m2z));
        float n2 = fmaf(b2x, b2x, fmaf(b2y, b2y, b2z * b2z));

        q0x = m0x; q0y = m0y; q0z = m0z;
        rescale3(n0, q0x, q0y, q0z, S0);
        q1x = b1x; q1y = b1y; q1z = b1z;
        rescale3(n1, q1x, q1y, q1z, S1);
        q2x = b2x; q2y = b2y; q2z = b2z;
        rescale3(n2, q2x, q2y, q2z, S2);

        // Segment boundary: exact-normalize Q, reset exponent counters
        if (g == segStart - 1) {
            float f0 = fmaf(q0x, q0x, fmaf(q0y, q0y, q0z * q0z));
            float f1 = fmaf(q1x, q1x, fmaf(q1y, q1y, q1z * q1z));
            float f2 = fmaf(q2x, q2x, fmaf(q2y, q2y, q2z * q2z));
            float i0 = 1.0f / sqrtf(f0);
            float i1 = 1.0f / sqrtf(f1);
            float i2 = 1.0f / sqrtf(f2);
            q0x *= i0; q0y *= i0; q0z *= i0;
            q1x *= i1; q1y *= i1; q1z *= i1;
            q2x *= i2; q2y *= i2; q2z *= i2;
            S0 = S1 = S2 = 0;
        }
    }

    const float LN2 = 0.69314718055994531f;
    float f0 = fmaf(q0x, q0x, fmaf(q0y, q0y, q0z * q0z));
    float f1 = fmaf(q1x, q1x, fmaf(q1y, q1y, q1z * q1z));
    float f2 = fmaf(q2x, q2x, fmaf(q2y, q2y, q2z * q2z));

    g_part[(0 * NSEG + s) * NB + b] = 0.5f * logf(f0) + (float)S0 * LN2;
    g_part[(1 * NSEG + s) * NB + b] = 0.5f * logf(f1) + (float)S1 * LN2;
    g_part[(2 * NSEG + s) * NB + b] = 0.5f * logf(f2) + (float)S2 * LN2;
}

// ---------------------------------------------------------------------------
// Deterministic reduction over segments. Launched with PDL: blocks schedule
// and run their preamble during the fused kernel's tail, then griddepcontrol
// .wait blocks until the fused grid (and its g_part stores) completes.
// ---------------------------------------------------------------------------
__global__ __launch_bounds__(128) void reduce_kernel(float* __restrict__ out) {
    int i = blockIdx.x * 128 + threadIdx.x;          // 0 .. 3*NB-1
    int c = i / NB;
    int b = i - c * NB;

    asm volatile("griddepcontrol.wait;" ::: "memory");   // PDL: primary done

    float sum = 0.f;
#pragma unroll
    for (int s = 0; s < NSEG; s++)
        sum += g_part[(c * NSEG + s) * NB + b];
    const float INV_TDT = 1.0f / ((float)T_STEPS * 0.01f);   // 1/40.96
    out[i] = sum * INV_TDT;
}

extern "C" void kernel_launch(void* const* d_in, const int* in_sizes, int n_in,
                              void* d_out, int out_size) {
    const float* inp = (const float*)d_in[0];
    float* out = (float*)d_out;
    (void)in_sizes; (void)n_in; (void)out_size;

    const int smem_bytes = DEPTH * 36 * 128 * sizeof(float);  // 73728 B
    static bool attr_done = false;  // idempotent host-side attribute, not a graph op
    if (!attr_done) {
        cudaFuncSetAttribute(fused_scan_kernel,
                             cudaFuncAttributeMaxDynamicSharedMemorySize, smem_bytes);
        attr_done = true;
    }

    dim3 g(NB / 128, NSEG);
    fused_scan_kernel<<<g, 128, smem_bytes>>>(inp);

    // Reduce via PDL so its launch+ramp overlaps the fused kernel's tail.
    cudaLaunchConfig_t cfg = {};
    cfg.gridDim  = dim3((3 * NB) / 128);
    cfg.blockDim = dim3(128);
    cfg.dynamicSmemBytes = 0;
    cfg.stream = 0;   // same (capture) stream as the primary launch
    cudaLaunchAttribute attrs[1];
    attrs[0].id = cudaLaunchAttributeProgrammaticStreamSerialization;
    attrs[0].val.programmaticStreamSerializationAllowed = 1;
    cfg.attrs = attrs;
    cfg.numAttrs = 1;
    cudaLaunchKernelEx(&cfg, reduce_kernel, out);
}

// round 8
// speedup vs baseline: 1.2917x; 1.0012x over previous
#include <cuda_runtime.h>
#include <math.h>

// Problem constants (inp shape (4096, 9, 2048) fp32, out (3, 2048) fp32)
#define T_STEPS 4096
#define NB      2048
#define CHUNK   4
#define NG      (T_STEPS / CHUNK)   // 1024 chunk-steps
#define NSEG    16
#define SEGLEN  (NG / NSEG)         // 64 chunks per segment
#define WARM    8                   // warmup chunks (32 raw steps)
#define DEPTH   4                   // smem pipeline depth (power of 2)

__device__ __forceinline__ float rcp_approx(float x) {
    float r;
    asm("rcp.approx.f32 %0, %1;" : "=f"(r) : "f"(x));
    return r;
}

__device__ __forceinline__ void rescale3(float nsq, float& x, float& y, float& z, int& S) {
    int e = (__float_as_int(nsq) >> 23) - 127;
    int s = e >> 1;                                  // floor(e/2)
    float sc = __int_as_float((127 - s) << 23);      // 2^{-s}
    x *= sc; y *= sc; z *= sc;
    S += s;
}

__device__ __forceinline__ void cp16(float* smem_dst, const float* gmem_src) {
    unsigned d = (unsigned)__cvta_generic_to_shared(smem_dst);
    asm volatile("cp.async.cg.shared.global [%0], [%1], 16;\n" :: "r"(d), "l"(gmem_src));
}

// ---------------------------------------------------------------------------
// Fused kernel with cp.async smem pipeline. Main loop BYTE-IDENTICAL to the
// 51.3us R7 version (at its DRAM traffic floor). Epilogue: each segment
// block fire-and-forget atomicAdds its scaled partial straight into out[]
// (out zeroed by a memset node at graph start). NO fences, NO counters —
// REDG imposes no ordering on the streaming loop (R5 lesson).
// ---------------------------------------------------------------------------
__global__ __launch_bounds__(128) void fused_scan_kernel(const float* __restrict__ inp,
                                                          float* __restrict__ out) {
    extern __shared__ float sbuf[];                  // [DEPTH][36][128]
    const int tid = threadIdx.x;
    const int b0  = blockIdx.x * 128;
    const int b   = b0 + tid;
    const int s   = blockIdx.y;
    const int segStart = s * SEGLEN;
    int g0 = segStart - WARM; if (g0 < 0) g0 = 0;
    const int gEnd = segStart + SEGLEN;

    // Q columns (identity start; warmed up for s>0)
    float q0x = 1.f, q0y = 0.f, q0z = 0.f;
    float q1x = 0.f, q1y = 1.f, q1z = 0.f;
    float q2x = 0.f, q2y = 0.f, q2z = 1.f;
    int S0 = 0, S1 = 0, S2 = 0;

    // Producer: stage chunk c into smem ring slot c & (DEPTH-1).
    auto issue_chunk = [&](int c) {
        int buf = c & (DEPTH - 1);
#pragma unroll
        for (int k = 0; k < 9; k++) {
            int idx = tid + k * 128;                 // 0..1151
            int j = idx >> 5;                        // plane 0..35
            int l = idx & 31;                        // 16B lane within row
            const float* src = inp + (size_t)(c * 36 + j) * NB + b0 + l * 4;
            float* dst = sbuf + ((buf * 36 + j) * 128 + l * 4);
            cp16(dst, src);
        }
        asm volatile("cp.async.commit_group;\n" ::: "memory");
    };

    // Prologue: fill the pipeline
#pragma unroll
    for (int c = 0; c < DEPTH; c++) issue_chunk(g0 + c);

    for (int g = g0; g < gEnd; g++) {
        asm volatile("cp.async.wait_group %0;\n" :: "n"(DEPTH - 1) : "memory");
        __syncthreads();                             // writes visible block-wide

        const float* J = sbuf + (size_t)(g & (DEPTH - 1)) * 36 * 128 + tid;

        // Apply 4 Jacobians to all three Q columns: Q <- J_t * Q
        float m0x = q0x, m0y = q0y, m0z = q0z;
        float m1x = q1x, m1y = q1y, m1z = q1z;
        float m2x = q2x, m2y = q2y, m2z = q2z;
#pragma unroll
        for (int t = 0; t < CHUNK; t++) {
            float j0 = J[(t*9+0)*128], j1 = J[(t*9+1)*128], j2 = J[(t*9+2)*128];
            float j3 = J[(t*9+3)*128], j4 = J[(t*9+4)*128], j5 = J[(t*9+5)*128];
            float j6 = J[(t*9+6)*128], j7 = J[(t*9+7)*128], j8 = J[(t*9+8)*128];
            float a0 = fmaf(j0, m0x, fmaf(j1, m0y, j2 * m0z));
            float a1 = fmaf(j3, m0x, fmaf(j4, m0y, j5 * m0z));
            float a2 = fmaf(j6, m0x, fmaf(j7, m0y, j8 * m0z));
            float c0 = fmaf(j0, m1x, fmaf(j1, m1y, j2 * m1z));
            float c1 = fmaf(j3, m1x, fmaf(j4, m1y, j5 * m1z));
            float c2 = fmaf(j6, m1x, fmaf(j7, m1y, j8 * m1z));
            float e0 = fmaf(j0, m2x, fmaf(j1, m2y, j2 * m2z));
            float e1 = fmaf(j3, m2x, fmaf(j4, m2y, j5 * m2z));
            float e2 = fmaf(j6, m2x, fmaf(j7, m2y, j8 * m2z));
            m0x = a0; m0y = a1; m0z = a2;
            m1x = c0; m1y = c1; m1z = c2;
            m2x = e0; m2y = e1; m2z = e2;
        }

        __syncthreads();                             // all threads done with slot
        if (g + DEPTH < gEnd) issue_chunk(g + DEPTH);
        else asm volatile("cp.async.commit_group;\n" ::: "memory");

        // Classical Gram-Schmidt (matches reference), unnormalized betas
        float n0 = fmaf(m0x, m0x, fmaf(m0y, m0y, m0z * m0z));
        float r0 = rcp_approx(n0);

        float d01 = fmaf(m0x, m1x, fmaf(m0y, m1y, m0z * m1z));
        float c01 = d01 * r0;
        float b1x = fmaf(-c01, m0x, m1x);
        float b1y = fmaf(-c01, m0y, m1y);
        float b1z = fmaf(-c01, m0z, m1z);
        float n1 = fmaf(b1x, b1x, fmaf(b1y, b1y, b1z * b1z));
        float r1 = rcp_approx(n1);

        float d02 = fmaf(m0x, m2x, fmaf(m0y, m2y, m0z * m2z));
        float c02 = d02 * r0;
        float d12 = fmaf(b1x, m2x, fmaf(b1y, m2y, b1z * m2z));
        float c12 = d12 * r1;
        float b2x = fmaf(-c12, b1x, fmaf(-c02, m0x, m2x));
        float b2y = fmaf(-c12, b1y, fmaf(-c02, m0y, m2y));
        float b2z = fmaf(-c12, b1z, fmaf(-c02, m0z, m2z));
        float n2 = fmaf(b2x, b2x, fmaf(b2y, b2y, b2z * b2z));

        q0x = m0x; q0y = m0y; q0z = m0z;
        rescale3(n0, q0x, q0y, q0z, S0);
        q1x = b1x; q1y = b1y; q1z = b1z;
        rescale3(n1, q1x, q1y, q1z, S1);
        q2x = b2x; q2y = b2y; q2z = b2z;
        rescale3(n2, q2x, q2y, q2z, S2);

        // Segment boundary: exact-normalize Q, reset exponent counters
        if (g == segStart - 1) {
            float f0 = fmaf(q0x, q0x, fmaf(q0y, q0y, q0z * q0z));
            float f1 = fmaf(q1x, q1x, fmaf(q1y, q1y, q1z * q1z));
            float f2 = fmaf(q2x, q2x, fmaf(q2y, q2y, q2z * q2z));
            float i0 = 1.0f / sqrtf(f0);
            float i1 = 1.0f / sqrtf(f1);
            float i2 = 1.0f / sqrtf(f2);
            q0x *= i0; q0y *= i0; q0z *= i0;
            q1x *= i1; q1y *= i1; q1z *= i1;
            q2x *= i2; q2y *= i2; q2z *= i2;
            S0 = S1 = S2 = 0;
        }
    }

    // ---- Epilogue: fire-and-forget atomic accumulation into out ----------
    const float LN2 = 0.69314718055994531f;
    const float INV_TDT = 1.0f / ((float)T_STEPS * 0.01f);   // 1/40.96
    float f0 = fmaf(q0x, q0x, fmaf(q0y, q0y, q0z * q0z));
    float f1 = fmaf(q1x, q1x, fmaf(q1y, q1y, q1z * q1z));
    float f2 = fmaf(q2x, q2x, fmaf(q2y, q2y, q2z * q2z));

    atomicAdd(&out[0 * NB + b], (0.5f * logf(f0) + (float)S0 * LN2) * INV_TDT);
    atomicAdd(&out[1 * NB + b], (0.5f * logf(f1) + (float)S1 * LN2) * INV_TDT);
    atomicAdd(&out[2 * NB + b], (0.5f * logf(f2) + (float)S2 * LN2) * INV_TDT);
}

extern "C" void kernel_launch(void* const* d_in, const int* in_sizes, int n_in,
                              void* d_out, int out_size) {
    const float* inp = (const float*)d_in[0];
    float* out = (float*)d_out;
    (void)in_sizes; (void)n_in; (void)out_size;

    const int smem_bytes = DEPTH * 36 * 128 * sizeof(float);  // 73728 B
    static bool attr_done = false;  // idempotent host-side attribute, not a graph op
    if (!attr_done) {
        cudaFuncSetAttribute(fused_scan_kernel,
                             cudaFuncAttributeMaxDynamicSharedMemorySize, smem_bytes);
        attr_done = true;
    }

    // Zero the (0xAA-poisoned) output; accumulation base for the atomics.
    cudaMemsetAsync(out, 0, 3 * NB * sizeof(float), 0);

    dim3 g(NB / 128, NSEG);
    fused_scan_kernel<<<g, 128, smem_bytes>>>(inp, out);
}

// round 9
// speedup vs baseline: 1.3265x; 1.0269x over previous
#include <cuda_runtime.h>
#include <math.h>

// Problem constants (inp shape (4096, 9, 2048) fp32, out (3, 2048) fp32)
#define T_STEPS 4096
#define NB      2048
#define CHUNK   4
#define NG      (T_STEPS / CHUNK)   // 1024 chunk-steps
#define NSEG    9                   // 16 bgrp x 9 seg = 144 blocks <= 148 SMs: ONE wave
#define WARM    8                   // warmup chunks (32 raw steps)
#define DEPTH   8                   // smem pipeline depth (power of 2); 147 KB smem

__device__ __forceinline__ float rcp_approx(float x) {
    float r;
    asm("rcp.approx.f32 %0, %1;" : "=f"(r) : "f"(x));
    return r;
}

__device__ __forceinline__ void rescale3(float nsq, float& x, float& y, float& z, int& S) {
    int e = (__float_as_int(nsq) >> 23) - 127;
    int s = e >> 1;                                  // floor(e/2)
    float sc = __int_as_float((127 - s) << 23);      // 2^{-s}
    x *= sc; y *= sc; z *= sc;
    S += s;
}

__device__ __forceinline__ void cp16(float* smem_dst, const float* gmem_src) {
    unsigned d = (unsigned)__cvta_generic_to_shared(smem_dst);
    asm volatile("cp.async.cg.shared.global [%0], [%1], 16;\n" :: "r"(d), "l"(gmem_src));
}

// ---------------------------------------------------------------------------
// Fused kernel, single-wave grid (144 blocks), DEPTH-8 cp.async smem ring.
// Segment boundaries are (s*NG)/NSEG (lengths differ by at most 1 chunk).
// Epilogue: fire-and-forget atomicAdd into out (zeroed by memset node).
// NO fences/counters in the kernel (R5 lesson); atomics alone are free (R8).
// ---------------------------------------------------------------------------
__global__ __launch_bounds__(128) void fused_scan_kernel(const float* __restrict__ inp,
                                                          float* __restrict__ out) {
    extern __shared__ float sbuf[];                  // [DEPTH][36][128]
    const int tid = threadIdx.x;
    const int b0  = blockIdx.x * 128;
    const int b   = b0 + tid;
    const int s   = blockIdx.y;
    const int segStart = (s * NG) / NSEG;
    const int segEnd   = ((s + 1) * NG) / NSEG;
    int g0 = segStart - WARM; if (g0 < 0) g0 = 0;
    const int gEnd = segEnd;

    // Q columns (identity start; warmed up for s>0)
    float q0x = 1.f, q0y = 0.f, q0z = 0.f;
    float q1x = 0.f, q1y = 1.f, q1z = 0.f;
    float q2x = 0.f, q2y = 0.f, q2z = 1.f;
    int S0 = 0, S1 = 0, S2 = 0;

    // Producer: stage chunk c into smem ring slot c & (DEPTH-1).
    auto issue_chunk = [&](int c) {
        int buf = c & (DEPTH - 1);
#pragma unroll
        for (int k = 0; k < 9; k++) {
            int idx = tid + k * 128;                 // 0..1151
            int j = idx >> 5;                        // plane 0..35
            int l = idx & 31;                        // 16B lane within row
            const float* src = inp + (size_t)(c * 36 + j) * NB + b0 + l * 4;
            float* dst = sbuf + ((buf * 36 + j) * 128 + l * 4);
            cp16(dst, src);
        }
        asm volatile("cp.async.commit_group;\n" ::: "memory");
    };

    // Prologue: fill the pipeline (segments are >= 113 chunks, >> DEPTH)
#pragma unroll
    for (int c = 0; c < DEPTH; c++) issue_chunk(g0 + c);

    for (int g = g0; g < gEnd; g++) {
        asm volatile("cp.async.wait_group %0;\n" :: "n"(DEPTH - 1) : "memory");
        __syncthreads();                             // writes visible block-wide

        const float* J = sbuf + (size_t)(g & (DEPTH - 1)) * 36 * 128 + tid;

        // Apply 4 Jacobians to all three Q columns: Q <- J_t * Q
        float m0x = q0x, m0y = q0y, m0z = q0z;
        float m1x = q1x, m1y = q1y, m1z = q1z;
        float m2x = q2x, m2y = q2y, m2z = q2z;
#pragma unroll
        for (int t = 0; t < CHUNK; t++) {
            float j0 = J[(t*9+0)*128], j1 = J[(t*9+1)*128], j2 = J[(t*9+2)*128];
            float j3 = J[(t*9+3)*128], j4 = J[(t*9+4)*128], j5 = J[(t*9+5)*128];
            float j6 = J[(t*9+6)*128], j7 = J[(t*9+7)*128], j8 = J[(t*9+8)*128];
            float a0 = fmaf(j0, m0x, fmaf(j1, m0y, j2 * m0z));
            float a1 = fmaf(j3, m0x, fmaf(j4, m0y, j5 * m0z));
            float a2 = fmaf(j6, m0x, fmaf(j7, m0y, j8 * m0z));
            float c0 = fmaf(j0, m1x, fmaf(j1, m1y, j2 * m1z));
            float c1 = fmaf(j3, m1x, fmaf(j4, m1y, j5 * m1z));
            float c2 = fmaf(j6, m1x, fmaf(j7, m1y, j8 * m1z));
            float e0 = fmaf(j0, m2x, fmaf(j1, m2y, j2 * m2z));
            float e1 = fmaf(j3, m2x, fmaf(j4, m2y, j5 * m2z));
            float e2 = fmaf(j6, m2x, fmaf(j7, m2y, j8 * m2z));
            m0x = a0; m0y = a1; m0z = a2;
            m1x = c0; m1y = c1; m1z = c2;
            m2x = e0; m2y = e1; m2z = e2;
        }

        __syncthreads();                             // all threads done with slot
        if (g + DEPTH < gEnd) issue_chunk(g + DEPTH);
        else asm volatile("cp.async.commit_group;\n" ::: "memory");

        // Classical Gram-Schmidt (matches reference), unnormalized betas
        float n0 = fmaf(m0x, m0x, fmaf(m0y, m0y, m0z * m0z));
        float r0 = rcp_approx(n0);

        float d01 = fmaf(m0x, m1x, fmaf(m0y, m1y, m0z * m1z));
        float c01 = d01 * r0;
        float b1x = fmaf(-c01, m0x, m1x);
        float b1y = fmaf(-c01, m0y, m1y);
        float b1z = fmaf(-c01, m0z, m1z);
        float n1 = fmaf(b1x, b1x, fmaf(b1y, b1y, b1z * b1z));
        float r1 = rcp_approx(n1);

        float d02 = fmaf(m0x, m2x, fmaf(m0y, m2y, m0z * m2z));
        float c02 = d02 * r0;
        float d12 = fmaf(b1x, m2x, fmaf(b1y, m2y, b1z * m2z));
        float c12 = d12 * r1;
        float b2x = fmaf(-c12, b1x, fmaf(-c02, m0x, m2x));
        float b2y = fmaf(-c12, b1y, fmaf(-c02, m0y, m2y));
        float b2z = fmaf(-c12, b1z, fmaf(-c02, m0z, m2z));
        float n2 = fmaf(b2x, b2x, fmaf(b2y, b2y, b2z * b2z));

        q0x = m0x; q0y = m0y; q0z = m0z;
        rescale3(n0, q0x, q0y, q0z, S0);
        q1x = b1x; q1y = b1y; q1z = b1z;
        rescale3(n1, q1x, q1y, q1z, S1);
        q2x = b2x; q2y = b2y; q2z = b2z;
        rescale3(n2, q2x, q2y, q2z, S2);

        // Segment boundary: exact-normalize Q, reset exponent counters
        if (g == segStart - 1) {
            float f0 = fmaf(q0x, q0x, fmaf(q0y, q0y, q0z * q0z));
            float f1 = fmaf(q1x, q1x, fmaf(q1y, q1y, q1z * q1z));
            float f2 = fmaf(q2x, q2x, fmaf(q2y, q2y, q2z * q2z));
            float i0 = 1.0f / sqrtf(f0);
            float i1 = 1.0f / sqrtf(f1);
            float i2 = 1.0f / sqrtf(f2);
            q0x *= i0; q0y *= i0; q0z *= i0;
            q1x *= i1; q1y *= i1; q1z *= i1;
            q2x *= i2; q2y *= i2; q2z *= i2;
            S0 = S1 = S2 = 0;
        }
    }

    // ---- Epilogue: fire-and-forget atomic accumulation into out ----------
    const float LN2 = 0.69314718055994531f;
    const float INV_TDT = 1.0f / ((float)T_STEPS * 0.01f);   // 1/40.96
    float f0 = fmaf(q0x, q0x, fmaf(q0y, q0y, q0z * q0z));
    float f1 = fmaf(q1x, q1x, fmaf(q1y, q1y, q1z * q1z));
    float f2 = fmaf(q2x, q2x, fmaf(q2y, q2y, q2z * q2z));

    atomicAdd(&out[0 * NB + b], (0.5f * logf(f0) + (float)S0 * LN2) * INV_TDT);
    atomicAdd(&out[1 * NB + b], (0.5f * logf(f1) + (float)S1 * LN2) * INV_TDT);
    atomicAdd(&out[2 * NB + b], (0.5f * logf(f2) + (float)S2 * LN2) * INV_TDT);
}

extern "C" void kernel_launch(void* const* d_in, const int* in_sizes, int n_in,
                              void* d_out, int out_size) {
    const float* inp = (const float*)d_in[0];
    float* out = (float*)d_out;
    (void)in_sizes; (void)n_in; (void)out_size;

    const int smem_bytes = DEPTH * 36 * 128 * sizeof(float);  // 147456 B
    static bool attr_done = false;  // idempotent host-side attribute, not a graph op
    if (!attr_done) {
        cudaFuncSetAttribute(fused_scan_kernel,
                             cudaFuncAttributeMaxDynamicSharedMemorySize, smem_bytes);
        attr_done = true;
    }

    // Zero the (0xAA-poisoned) output; accumulation base for the atomics.
    cudaMemsetAsync(out, 0, 3 * NB * sizeof(float), 0);

    dim3 g(NB / 128, NSEG);
    fused_scan_kernel<<<g, 128, smem_bytes>>>(inp, out);
}